// round 1
// baseline (speedup 1.0000x reference)
#include <cuda_runtime.h>
#include <cstdint>

// ---------------------------------------------------------------------------
// SSD post-processing:
//   inputs:  loc [32,8732,4] f32, conf [32,8732,21] f32, priors [8732,4] f32
//   output:  [32,21,200,5] f32  rows = [score, x1, y1, x2, y2]
// ---------------------------------------------------------------------------

#define BATCH 32
#define NPRI  8732
#define NCLS  21
#define TOPK  200
#define NSORT 512
#define SUPW  8
#define CONF_T 0.01f
#define NMS_T  0.45f

// shared-memory layout for the select/NMS kernel (byte offsets)
#define OFF_KEY  0
#define OFF_SEL  ((NPRI*4 + 15) & ~15)          /* 34944 */
#define OFF_HIST (OFF_SEL + NSORT*8)            /* 39040 */
#define OFF_SUP  (OFF_HIST + 256*4)             /* 40064 */
#define OFF_SSC  (OFF_SUP + TOPK*SUPW*4)        /* 46464 */
#define OFF_SX1  (OFF_SSC + TOPK*4)
#define OFF_SY1  (OFF_SX1 + TOPK*4)
#define OFF_SX2  (OFF_SY1 + TOPK*4)
#define OFF_SY2  (OFF_SX2 + TOPK*4)
#define OFF_POS  (OFF_SY2 + TOPK*4)
#define OFF_SH   (OFF_POS + TOPK*4)
#define SMEM_B   (OFF_SH + 64)                  /* ~51.4 KB */

// scratch (module-load allocated, not runtime alloc)
__device__ uint32_t g_keys[BATCH][NCLS-1][NPRI];
__device__ float4   g_boxes[BATCH][NPRI];

// ---------------------------------------------------------------------------
// Kernel A: softmax over 21 classes + box decode. One thread per (b, prior).
// Writes class-major masked keys (float bits of score if fully valid, else 0)
// so the selection kernel gets contiguous per-class score arrays.
// ---------------------------------------------------------------------------
__global__ __launch_bounds__(256) void ssd_decode_softmax(
    const float* __restrict__ loc,
    const float* __restrict__ conf,
    const float* __restrict__ priors)
{
    int t = blockIdx.x * blockDim.x + threadIdx.x;
    if (t >= BATCH * NPRI) return;
    int b = t / NPRI;
    int p = t - b * NPRI;

    // ---- softmax (clip +-100, subtract max, exp, divide) ----
    const float* cf = conf + (size_t)t * NCLS;
    float v[NCLS];
    float m = -1e30f;
#pragma unroll
    for (int c = 0; c < NCLS; c++) {
        float x = cf[c];
        x = fminf(fmaxf(x, -100.0f), 100.0f);
        v[c] = x;
        m = fmaxf(m, x);
    }
    float s = 0.0f;
#pragma unroll
    for (int c = 0; c < NCLS; c++) { v[c] = expf(v[c] - m); s += v[c]; }

    // ---- decode ----
    const float* lp = loc + (size_t)t * 4;
    const float* pr = priors + (size_t)p * 4;
    float p0 = fmaxf(pr[0], 1e-6f);
    float p1 = fmaxf(pr[1], 1e-6f);
    float p2 = fmaxf(pr[2], 1e-6f);
    float p3 = fmaxf(pr[3], 1e-6f);
    float cx = p0 + lp[0] * 0.1f * p2;
    float cy = p1 + lp[1] * 0.1f * p3;
    float lw = fminf(fmaxf(lp[2] * 0.2f, -4.0f), 4.0f);
    float lh = fminf(fmaxf(lp[3] * 0.2f, -4.0f), 4.0f);
    float w = p2 * expf(lw);
    float h = p3 * expf(lh);
    float x1 = fminf(fmaxf(cx - w / 2.0f, 0.0f), 1.0f);
    float y1 = fminf(fmaxf(cy - h / 2.0f, 0.0f), 1.0f);
    float x2 = fminf(fmaxf(cx + w / 2.0f, 0.0f), 1.0f);
    float y2 = fminf(fmaxf(cy + h / 2.0f, 0.0f), 1.0f);
    g_boxes[b][p] = make_float4(x1, y1, x2, y2);

    bool bvalid = (x2 > x1 + 1e-6f) && (y2 > y1 + 1e-6f);
#pragma unroll
    for (int c = 1; c < NCLS; c++) {
        float sc = v[c] / s;                       // matches softmax divide
        uint32_t key = (bvalid && sc > CONF_T) ? __float_as_uint(sc) : 0u;
        g_keys[b][c - 1][p] = key;
    }
}

// ---------------------------------------------------------------------------
// Kernel B: per (image, class): exact top-200 (radix select + bitonic sort for
// ordering with index tie-break), sequential NMS via suppression bitmask,
// compaction, output write. One 256-thread block per (b, c).
// ---------------------------------------------------------------------------
__global__ __launch_bounds__(256) void ssd_select_nms(float* __restrict__ out)
{
    int bc = blockIdx.x;
    int b = bc / NCLS;
    int c = bc - b * NCLS;
    int tid = threadIdx.x;
    float* orow = out + ((size_t)b * NCLS + c) * TOPK * 5;

    if (c == 0) {   // background class: all zeros
        for (int i = tid; i < TOPK * 5; i += 256) orow[i] = 0.0f;
        return;
    }

    extern __shared__ uint8_t smem[];
    uint32_t* skey = (uint32_t*)(smem + OFF_KEY);
    uint64_t* sel  = (uint64_t*)(smem + OFF_SEL);
    int*      hist = (int*)(smem + OFF_HIST);
    uint32_t* sup  = (uint32_t*)(smem + OFF_SUP);
    float*    ssc  = (float*)(smem + OFF_SSC);
    float*    sx1  = (float*)(smem + OFF_SX1);
    float*    sy1  = (float*)(smem + OFF_SY1);
    float*    sx2  = (float*)(smem + OFF_SX2);
    float*    sy2  = (float*)(smem + OFF_SY2);
    int*      spos = (int*)(smem + OFF_POS);
    int*      sh   = (int*)(smem + OFF_SH);

    // ---- load masked keys into shared ----
    const uint32_t* gk = &g_keys[b][c - 1][0];
    for (int i = tid; i < NPRI; i += 256) skey[i] = gk[i];
    __syncthreads();

    // ---- radix select: find the 200th-largest key (threshold) ----
    uint32_t prefix = 0;
    int remaining = TOPK;
    for (int shift = 24; shift >= 0; shift -= 8) {
        hist[tid] = 0;
        __syncthreads();
        uint32_t pmask = (shift == 24) ? 0u : (0xFFFFFFFFu << (shift + 8));
        for (int i = tid; i < NPRI; i += 256) {
            uint32_t k = skey[i];
            if ((k & pmask) == prefix)
                atomicAdd(&hist[(k >> shift) & 0xFF], 1);
        }
        __syncthreads();
        if (tid == 0) {
            int cum = 0;
            int d = 255;
            for (; d > 0; d--) {
                int hh = hist[d];
                if (cum + hh >= remaining) break;
                cum += hh;
            }
            sh[0] = d;
            sh[1] = cum;
        }
        __syncthreads();
        prefix |= ((uint32_t)sh[0]) << shift;
        remaining -= sh[1];
        __syncthreads();
    }
    uint32_t thr = prefix;   // key value of the 200th-largest (0 if <200 valid)

    // ---- collect candidates >= threshold ----
    if (tid == 0) sh[2] = 0;
    __syncthreads();
    for (int i = tid; i < NPRI; i += 256) {
        uint32_t k = skey[i];
        bool take = thr ? (k >= thr) : (k > 0u);
        if (take) {
            int pos = atomicAdd(&sh[2], 1);
            if (pos < NSORT)
                sel[pos] = ((uint64_t)k << 32) | (uint32_t)(~(uint32_t)i);
        }
    }
    __syncthreads();
    int nsel = sh[2];
    if (nsel > NSORT) nsel = NSORT;
    for (int i = tid; i < NSORT; i += 256)
        if (i >= nsel) sel[i] = 0ull;

    // ---- bitonic sort descending (key desc, index asc via ~idx low word) ----
    for (int kk = 2; kk <= NSORT; kk <<= 1) {
        for (int j = kk >> 1; j > 0; j >>= 1) {
            __syncthreads();
            for (int i = tid; i < NSORT; i += 256) {
                int ixj = i ^ j;
                if (ixj > i) {
                    uint64_t a = sel[i], bb = sel[ixj];
                    bool up = (i & kk) == 0;   // descending order
                    if (up ? (a < bb) : (a > bb)) { sel[i] = bb; sel[ixj] = a; }
                }
            }
        }
    }
    __syncthreads();

    // ---- gather top-200 boxes & scores ----
    for (int i = tid; i < TOPK; i += 256) {
        uint64_t e = sel[i];
        uint32_t k = (uint32_t)(e >> 32);
        float sc; float4 bx;
        if (k) {
            uint32_t idx = ~(uint32_t)e;
            sc = __uint_as_float(k);
            bx = g_boxes[b][idx];
        } else {
            sc = -1.0f;
            bx = make_float4(0.f, 0.f, 0.f, 0.f);
        }
        ssc[i] = sc; sx1[i] = bx.x; sy1[i] = bx.y; sx2[i] = bx.z; sy2[i] = bx.w;
    }
    for (int i = tid; i < TOPK * SUPW; i += 256) sup[i] = 0u;
    __syncthreads();

    // ---- IoU suppression bitmask (i suppresses j>i when iou > thresh) ----
    for (int t = tid; t < TOPK * TOPK; t += 256) {
        int i = t / TOPK;
        int j = t - i * TOPK;
        if (j <= i) continue;
        if (ssc[i] <= 0.0f || ssc[j] <= 0.0f) continue;
        float xx1 = fmaxf(sx1[i], sx1[j]);
        float yy1 = fmaxf(sy1[i], sy1[j]);
        float xx2 = fminf(sx2[i], sx2[j]);
        float yy2 = fminf(sy2[i], sy2[j]);
        float w = fmaxf(xx2 - xx1, 0.0f);
        float h = fmaxf(yy2 - yy1, 0.0f);
        float inter = w * h;
        float ai = (sx2[i] - sx1[i]) * (sy2[i] - sy1[i]);
        float aj = (sx2[j] - sx1[j]) * (sy2[j] - sy1[j]);
        float uni = ai + aj - inter;
        float iou = inter / fmaxf(uni, 1e-12f);
        if (iou > NMS_T)
            atomicOr(&sup[i * SUPW + (j >> 5)], 1u << (j & 31));
    }
    __syncthreads();

    // ---- sequential NMS sweep + compaction positions (one thread) ----
    if (tid == 0) {
        uint32_t al[SUPW];
#pragma unroll
        for (int w = 0; w < SUPW; w++) al[w] = 0xFFFFFFFFu;
        for (int i = 0; i < TOPK; i++) {
            if (((al[i >> 5] >> (i & 31)) & 1u) && ssc[i] > 0.0f) {
#pragma unroll
                for (int w = 0; w < SUPW; w++) al[w] &= ~sup[i * SUPW + w];
            }
        }
        int cnt = 0;
        for (int i = 0; i < TOPK; i++) {
            bool kp = (((al[i >> 5] >> (i & 31)) & 1u) != 0) && (ssc[i] > 0.0f);
            spos[i] = kp ? cnt++ : -1;
        }
    }
    // zero output region while thread 0 works
    for (int i = tid; i < TOPK * 5; i += 256) orow[i] = 0.0f;
    __syncthreads();

    // ---- write kept rows compacted to front ----
    for (int i = tid; i < TOPK; i += 256) {
        int q = spos[i];
        if (q >= 0) {
            float* r = orow + q * 5;
            r[0] = ssc[i];
            r[1] = sx1[i];
            r[2] = sy1[i];
            r[3] = sx2[i];
            r[4] = sy2[i];
        }
    }
}

// ---------------------------------------------------------------------------
extern "C" void kernel_launch(void* const* d_in, const int* in_sizes, int n_in,
                              void* d_out, int out_size)
{
    const float* loc    = (const float*)d_in[0];
    const float* conf   = (const float*)d_in[1];
    const float* priors = (const float*)d_in[2];
    float* out = (float*)d_out;

    cudaFuncSetAttribute(ssd_select_nms,
                         cudaFuncAttributeMaxDynamicSharedMemorySize, SMEM_B);

    ssd_decode_softmax<<<(BATCH * NPRI + 255) / 256, 256>>>(loc, conf, priors);
    ssd_select_nms<<<BATCH * NCLS, 256, SMEM_B>>>(out);
}

// round 2
// speedup vs baseline: 2.0256x; 2.0256x over previous
#include <cuda_runtime.h>
#include <cstdint>

// ---------------------------------------------------------------------------
// SSD post-processing:
//   inputs:  loc [32,8732,4] f32, conf [32,8732,21] f32, priors [8732,4] f32
//   output:  [32,21,200,5] f32  rows = [score, x1, y1, x2, y2]
// ---------------------------------------------------------------------------

#define BATCH 32
#define NPRI  8732
#define NPRI4 2183          /* 8732 / 4 exactly */
#define NCLS  21
#define TOPK  200
#define CAP   256           /* candidate capacity (common path) */
#define NW    7             /* ceil(200/32) suppression words */
#define SUPW  8             /* padded row width */
#define CONF_T 0.01f
#define NMS_T  0.45f
#define BASE16 0x3C00u      /* float bits of 0.0078 >> 16; all valid keys above */

// scratch (module-load allocated, not runtime alloc)
__device__ __align__(16) uint32_t g_keys[BATCH][NCLS-1][NPRI];
__device__ float4 g_boxes[BATCH][NPRI];

// ---------------------------------------------------------------------------
// Kernel A: softmax over 21 classes + box decode. One thread per (b, prior).
// ---------------------------------------------------------------------------
__global__ __launch_bounds__(256) void ssd_decode_softmax(
    const float* __restrict__ loc,
    const float* __restrict__ conf,
    const float* __restrict__ priors)
{
    int t = blockIdx.x * blockDim.x + threadIdx.x;
    if (t >= BATCH * NPRI) return;
    int b = t / NPRI;
    int p = t - b * NPRI;

    const float* cf = conf + (size_t)t * NCLS;
    float v[NCLS];
    float m = -1e30f;
#pragma unroll
    for (int c = 0; c < NCLS; c++) {
        float x = cf[c];
        x = fminf(fmaxf(x, -100.0f), 100.0f);
        v[c] = x;
        m = fmaxf(m, x);
    }
    float s = 0.0f;
#pragma unroll
    for (int c = 0; c < NCLS; c++) { v[c] = expf(v[c] - m); s += v[c]; }

    const float* lp = loc + (size_t)t * 4;
    const float* pr = priors + (size_t)p * 4;
    float p0 = fmaxf(pr[0], 1e-6f);
    float p1 = fmaxf(pr[1], 1e-6f);
    float p2 = fmaxf(pr[2], 1e-6f);
    float p3 = fmaxf(pr[3], 1e-6f);
    float cx = p0 + lp[0] * 0.1f * p2;
    float cy = p1 + lp[1] * 0.1f * p3;
    float lw = fminf(fmaxf(lp[2] * 0.2f, -4.0f), 4.0f);
    float lh = fminf(fmaxf(lp[3] * 0.2f, -4.0f), 4.0f);
    float w = p2 * expf(lw);
    float h = p3 * expf(lh);
    float x1 = fminf(fmaxf(cx - w / 2.0f, 0.0f), 1.0f);
    float y1 = fminf(fmaxf(cy - h / 2.0f, 0.0f), 1.0f);
    float x2 = fminf(fmaxf(cx + w / 2.0f, 0.0f), 1.0f);
    float y2 = fminf(fmaxf(cy + h / 2.0f, 0.0f), 1.0f);
    g_boxes[b][p] = make_float4(x1, y1, x2, y2);

    bool bvalid = (x2 > x1 + 1e-6f) && (y2 > y1 + 1e-6f);
#pragma unroll
    for (int c = 1; c < NCLS; c++) {
        float sc = v[c] / s;
        uint32_t key = (bvalid && sc > CONF_T) ? __float_as_uint(sc) : 0u;
        g_keys[b][c - 1][p] = key;
    }
}

// ---------------------------------------------------------------------------
// Kernel B: per (image,class) top-200 (16-bit histogram select + O(n^2) rank
// ordering), NMS bitmask, serial sweep, compaction. 256 threads / block,
// keys scanned straight from L2 (no smem staging) -> ~19KB smem, 8 blocks/SM.
// ---------------------------------------------------------------------------
__global__ __launch_bounds__(256, 8) void ssd_select_nms(float* __restrict__ out)
{
    __shared__ unsigned long long spk[CAP];
    __shared__ int hist[1024];
    __shared__ int part[256];
    __shared__ uint32_t sup[TOPK * SUPW];
    __shared__ float ssc[TOPK], sx1[TOPK], sy1[TOPK], sx2[TOPK], sy2[TOPK], sar[TOPK];
    __shared__ int spos[TOPK];
    __shared__ int sh[8];

    int bc = blockIdx.x;
    int b = bc / NCLS;
    int c = bc - b * NCLS;
    int tid = threadIdx.x;
    float* orow = out + (size_t)bc * (TOPK * 5);

    if (c == 0) {
        for (int i = tid; i < TOPK * 5; i += 256) orow[i] = 0.0f;
        return;
    }

    const uint32_t* gk = &g_keys[b][c - 1][0];
    const uint4* gk4 = (const uint4*)gk;

    // ---- pass 1: 16-bit digit histogram (skip zero keys) ----
    hist[tid] = 0; hist[tid + 256] = 0; hist[tid + 512] = 0; hist[tid + 768] = 0;
    __syncthreads();
    for (int i = tid; i < NPRI4; i += 256) {
        uint4 v = gk4[i];
        if (v.x) atomicAdd(&hist[(v.x >> 16) - BASE16], 1);
        if (v.y) atomicAdd(&hist[(v.y >> 16) - BASE16], 1);
        if (v.z) atomicAdd(&hist[(v.z >> 16) - BASE16], 1);
        if (v.w) atomicAdd(&hist[(v.w >> 16) - BASE16], 1);
    }
    __syncthreads();
    part[tid] = hist[4 * tid] + hist[4 * tid + 1] + hist[4 * tid + 2] + hist[4 * tid + 3];
    __syncthreads();

    // ---- warp suffix-scan over 32 coarse groups to locate the 200th digit ----
    if (tid < 32) {
        int s = 0;
#pragma unroll
        for (int q = 0; q < 8; q++) s += part[tid * 8 + q];
        int suf = s;
#pragma unroll
        for (int d = 1; d < 32; d <<= 1) {
            int o = __shfl_down_sync(0xFFFFFFFFu, suf, d);
            if (tid + d < 32) suf += o;
        }
        int sufN = __shfl_down_sync(0xFFFFFFFFu, suf, 1);
        if (tid == 31) sufN = 0;
        if (tid == 0) { sh[2] = suf; sh[0] = -1; }      // total; default take-all
        __syncwarp();
        if (suf >= TOPK && sufN < TOPK) { sh[0] = tid; sh[1] = sufN; }
        __syncwarp();
        if (tid == 0 && sh[0] >= 0) {
            int cum = sh[1];
            int d = sh[0] * 32 + 31;
            for (;; d--) { cum += hist[d]; if (cum >= TOPK) break; }
            sh[3] = d;                // offset digit of 200th value
            sh[4] = cum - hist[d];    // count with digit > d
            sh[5] = hist[d];
        }
    }
    __syncthreads();

    int ncand;
    bool rare = (sh[0] >= 0) && (sh[4] + sh[5] > CAP);
    if (!rare) {
        // ---- common path: collect all keys >= bucket floor (<= 256) ----
        uint32_t thrK = (sh[0] < 0) ? (BASE16 << 16)
                                    : ((uint32_t)(BASE16 + (uint32_t)sh[3]) << 16);
        if (tid == 0) sh[6] = 0;
        __syncthreads();
        for (int i = tid; i < NPRI4; i += 256) {
            uint4 v = gk4[i];
            int base = i * 4;
            if (v.x >= thrK) { int p = atomicAdd(&sh[6], 1); spk[p] = ((unsigned long long)v.x << 32) | (uint32_t)~(uint32_t)(base + 0); }
            if (v.y >= thrK) { int p = atomicAdd(&sh[6], 1); spk[p] = ((unsigned long long)v.y << 32) | (uint32_t)~(uint32_t)(base + 1); }
            if (v.z >= thrK) { int p = atomicAdd(&sh[6], 1); spk[p] = ((unsigned long long)v.z << 32) | (uint32_t)~(uint32_t)(base + 2); }
            if (v.w >= thrK) { int p = atomicAdd(&sh[6], 1); spk[p] = ((unsigned long long)v.w << 32) | (uint32_t)~(uint32_t)(base + 3); }
        }
        __syncthreads();
        ncand = sh[6];
    } else {
        // ---- rare path (massive ties): refine to exact 32-bit threshold ----
        uint32_t top16 = BASE16 + (uint32_t)sh[3];
        int cnt_gt = sh[4];
        hist[tid] = 0;
        __syncthreads();
        for (int i = tid; i < NPRI; i += 256) {
            uint32_t k = gk[i];
            if ((k >> 16) == top16) atomicAdd(&hist[(k >> 8) & 0xFF], 1);
        }
        __syncthreads();
        if (tid == 0) {
            int cum = cnt_gt; int d = 255;
            for (;; d--) { cum += hist[d]; if (cum >= TOPK) break; }
            sh[3] = d; sh[4] = cum - hist[d];
        }
        __syncthreads();
        uint32_t pre24 = (top16 << 8) | (uint32_t)sh[3];
        cnt_gt = sh[4];
        hist[tid] = 0;
        __syncthreads();
        for (int i = tid; i < NPRI; i += 256) {
            uint32_t k = gk[i];
            if ((k >> 8) == pre24) atomicAdd(&hist[k & 0xFF], 1);
        }
        __syncthreads();
        if (tid == 0) {
            int cum = cnt_gt; int d = 255;
            for (;; d--) { cum += hist[d]; if (cum >= TOPK) break; }
            sh[3] = d; sh[4] = cum - hist[d];
        }
        __syncthreads();
        uint32_t thr = (pre24 << 8) | (uint32_t)sh[3];
        if (tid == 0) sh[6] = 0;
        __syncthreads();
        for (int i = tid; i < NPRI; i += 256) {
            uint32_t k = gk[i];
            if (k > thr) { int p = atomicAdd(&sh[6], 1); spk[p] = ((unsigned long long)k << 32) | (uint32_t)~(uint32_t)i; }
        }
        __syncthreads();
        if (tid == 0) {   // append ties in ascending index order
            int p = sh[6];
            for (int i = 0; i < NPRI && p < TOPK; i++)
                if (gk[i] == thr) { spk[p++] = ((unsigned long long)thr << 32) | (uint32_t)~(uint32_t)i; }
            sh[6] = p;
        }
        __syncthreads();
        ncand = sh[6];
    }

    // ---- exact ordering via O(n^2) rank (key desc, index asc) ----
    for (int i = tid; i < TOPK; i += 256) ssc[i] = -1.0f;
    unsigned long long mypk = (tid < ncand) ? spk[tid] : 0ull;
    __syncthreads();
    if (tid < ncand) {
        int rank = 0;
        for (int j = 0; j < ncand; j++) rank += (spk[j] > mypk) ? 1 : 0;
        if (rank < TOPK) {
            uint32_t kk = (uint32_t)(mypk >> 32);
            uint32_t idx = ~(uint32_t)mypk;
            float4 bx = g_boxes[b][idx];
            ssc[rank] = __uint_as_float(kk);
            sx1[rank] = bx.x; sy1[rank] = bx.y; sx2[rank] = bx.z; sy2[rank] = bx.w;
            sar[rank] = (bx.z - bx.x) * (bx.w - bx.y);
        }
    }
    __syncthreads();
    int nval = ncand < TOPK ? ncand : TOPK;

    // ---- IoU suppression mask rows (thread i builds its word row) ----
    if (tid < nval) {
        float ax1 = sx1[tid], ay1 = sy1[tid], ax2 = sx2[tid], ay2 = sy2[tid];
        float aa = sar[tid];
        int wlo = tid >> 5;
        for (int w = 0; w < wlo; w++) sup[tid * SUPW + w] = 0u;
        for (int w = wlo; w < NW; w++) {
            uint32_t m = 0;
            int j0 = w * 32;
#pragma unroll 4
            for (int jj = 0; jj < 32; jj++) {
                int j = j0 + jj;
                if (j < nval && j > tid) {
                    float xx1 = fmaxf(ax1, sx1[j]);
                    float yy1 = fmaxf(ay1, sy1[j]);
                    float xx2 = fminf(ax2, sx2[j]);
                    float yy2 = fminf(ay2, sy2[j]);
                    float iw = fmaxf(xx2 - xx1, 0.0f);
                    float ih = fmaxf(yy2 - yy1, 0.0f);
                    float inter = iw * ih;
                    float uni = aa + sar[j] - inter;
                    float iou = inter / fmaxf(uni, 1e-12f);   // IEEE div: match ref
                    if (iou > NMS_T) m |= 1u << jj;
                }
            }
            sup[tid * SUPW + w] = m;
        }
    }
    // zero output region while mask finishes / sweep runs
    for (int i = tid; i < TOPK * 5; i += 256) orow[i] = 0.0f;
    __syncthreads();

    // ---- sequential NMS sweep + compaction positions (thread 0, reg-resident) ----
    if (tid == 0) {
        uint32_t alv[NW];
#pragma unroll
        for (int w = 0; w < NW; w++) alv[w] = 0xFFFFFFFFu;
#pragma unroll
        for (int g = 0; g < NW; g++) {
            for (int bit = 0; bit < 32; bit++) {
                int i = g * 32 + bit;
                if (i >= nval) break;
                if ((alv[g] >> bit) & 1u) {
#pragma unroll
                    for (int w = 0; w < NW; w++) alv[w] &= ~sup[i * SUPW + w];
                }
            }
        }
        int cnt = 0;
#pragma unroll
        for (int g = 0; g < NW; g++) {
            uint32_t aw = alv[g];
            for (int bit = 0; bit < 32; bit++) {
                int i = g * 32 + bit;
                if (i >= nval) break;
                spos[i] = ((aw >> bit) & 1u) ? cnt++ : -1;
            }
        }
    }
    __syncthreads();

    // ---- write kept rows compacted to front ----
    for (int i = tid; i < nval; i += 256) {
        int q = spos[i];
        if (q >= 0) {
            float* r = orow + q * 5;
            r[0] = ssc[i];
            r[1] = sx1[i];
            r[2] = sy1[i];
            r[3] = sx2[i];
            r[4] = sy2[i];
        }
    }
}

// ---------------------------------------------------------------------------
extern "C" void kernel_launch(void* const* d_in, const int* in_sizes, int n_in,
                              void* d_out, int out_size)
{
    const float* loc    = (const float*)d_in[0];
    const float* conf   = (const float*)d_in[1];
    const float* priors = (const float*)d_in[2];
    float* out = (float*)d_out;

    ssd_decode_softmax<<<(BATCH * NPRI + 255) / 256, 256>>>(loc, conf, priors);
    ssd_select_nms<<<BATCH * NCLS, 256>>>(out);
}

// round 3
// speedup vs baseline: 2.2349x; 1.1033x over previous
#include <cuda_runtime.h>
#include <cstdint>

// ---------------------------------------------------------------------------
// SSD post-processing:
//   inputs:  loc [32,8732,4] f32, conf [32,8732,21] f32, priors [8732,4] f32
//   output:  [32,21,200,5] f32  rows = [score, x1, y1, x2, y2]
// ---------------------------------------------------------------------------

#define BATCH 32
#define NPRI  8732
#define NPRI4 2183          /* 8732 / 4 exactly */
#define NCLS  21
#define TOPK  200
#define CAP   256           /* candidate capacity (common path) */
#define NW    7             /* ceil(200/32) suppression words */
#define SUPW  8             /* padded row width */
#define NTB   384           /* threads per select block */
#define CONF_T 0.01f
#define NMS_T  0.45f
#define NMS_HI 0.45000180f  /* 0.45*(1+4e-6) */
#define NMS_LO 0.44999820f  /* 0.45*(1-4e-6) */
#define BASE16 0x3C00u      /* top16 of float bits; all valid keys above this */

// scratch (module-load allocated & zero-initialized; kernel B self-cleans g_hist)
__device__ __align__(16) uint32_t g_keys[BATCH][NCLS-1][NPRI];
__device__ float4 g_boxes[BATCH][NPRI];
__device__ __align__(16) int g_hist[BATCH][NCLS-1][1024];

// ---------------------------------------------------------------------------
// Kernel A: softmax + decode + per-(b,c) 16-bit-digit histogram (REDG).
// One thread per (b, prior). Memory-roofline bound (~55MB traffic).
// ---------------------------------------------------------------------------
__global__ __launch_bounds__(256) void ssd_decode_softmax(
    const float* __restrict__ loc,
    const float* __restrict__ conf,
    const float* __restrict__ priors)
{
    int t = blockIdx.x * blockDim.x + threadIdx.x;
    if (t >= BATCH * NPRI) return;
    int b = t / NPRI;
    int p = t - b * NPRI;

    const float* cf = conf + (size_t)t * NCLS;
    float v[NCLS];
    float m = -1e30f;
#pragma unroll
    for (int c = 0; c < NCLS; c++) {
        float x = cf[c];
        x = fminf(fmaxf(x, -100.0f), 100.0f);
        v[c] = x;
        m = fmaxf(m, x);
    }
    float s = 0.0f;
#pragma unroll
    for (int c = 0; c < NCLS; c++) { v[c] = expf(v[c] - m); s += v[c]; }

    const float* lp = loc + (size_t)t * 4;
    const float* pr = priors + (size_t)p * 4;
    float p0 = fmaxf(pr[0], 1e-6f);
    float p1 = fmaxf(pr[1], 1e-6f);
    float p2 = fmaxf(pr[2], 1e-6f);
    float p3 = fmaxf(pr[3], 1e-6f);
    float cx = p0 + lp[0] * 0.1f * p2;
    float cy = p1 + lp[1] * 0.1f * p3;
    float lw = fminf(fmaxf(lp[2] * 0.2f, -4.0f), 4.0f);
    float lh = fminf(fmaxf(lp[3] * 0.2f, -4.0f), 4.0f);
    float w = p2 * expf(lw);
    float h = p3 * expf(lh);
    float x1 = fminf(fmaxf(cx - w / 2.0f, 0.0f), 1.0f);
    float y1 = fminf(fmaxf(cy - h / 2.0f, 0.0f), 1.0f);
    float x2 = fminf(fmaxf(cx + w / 2.0f, 0.0f), 1.0f);
    float y2 = fminf(fmaxf(cy + h / 2.0f, 0.0f), 1.0f);
    g_boxes[b][p] = make_float4(x1, y1, x2, y2);

    bool bvalid = (x2 > x1 + 1e-6f) && (y2 > y1 + 1e-6f);
#pragma unroll
    for (int c = 1; c < NCLS; c++) {
        float sc = v[c] / s;
        uint32_t key = (bvalid && sc > CONF_T) ? __float_as_uint(sc) : 0u;
        g_keys[b][c - 1][p] = key;
        if (key) atomicAdd(&g_hist[b][c - 1][(key >> 16) - BASE16], 1);
    }
}

// ---------------------------------------------------------------------------
// Kernel B: per (image,class): threshold from precomputed histogram, one
// collect scan, O(n^2) exact rank, split-row IoU mask, serial sweep,
// compaction. 384 threads, 5 blocks/SM (one full wave for 672 blocks).
// ---------------------------------------------------------------------------
__global__ __launch_bounds__(NTB, 5) void ssd_select_nms(float* __restrict__ out)
{
    __shared__ int hist[1024];
    __shared__ int part[256];
    __shared__ unsigned long long spk[CAP];
    __shared__ uint32_t sup[TOPK * SUPW];
    __shared__ float4 sbx[TOPK];
    __shared__ float sar[TOPK], ssc[TOPK];
    __shared__ int spos[TOPK];
    __shared__ int sh[8];

    int bc = blockIdx.x;
    int b = bc / NCLS;
    int c = bc - b * NCLS;
    int tid = threadIdx.x;
    float* orow = out + (size_t)bc * (TOPK * 5);

    if (c == 0) {
        for (int i = tid; i < TOPK * 5; i += NTB) orow[i] = 0.0f;
        return;
    }

    const uint32_t* gk = &g_keys[b][c - 1][0];
    const uint4* gk4 = (const uint4*)gk;
    int* gh = &g_hist[b][c - 1][0];

    // ---- P0: load precomputed histogram into smem + partial sums ----
    if (tid < 256) {
        uint4 h4 = ((const uint4*)gh)[tid];
        ((uint4*)hist)[tid] = h4;
        part[tid] = (int)(h4.x + h4.y + h4.z + h4.w);
    }
    __syncthreads();

    // ---- P1: zero g_hist for next graph replay; warp 0 finds 200th digit ----
    if (tid >= 256) {
        uint4 z = make_uint4(0u, 0u, 0u, 0u);
        ((uint4*)gh)[tid - 256] = z;
        ((uint4*)gh)[tid - 128] = z;
    }
    if (tid < 32) {
        int s = 0;
#pragma unroll
        for (int q = 0; q < 8; q++) s += part[tid * 8 + q];
        int suf = s;
#pragma unroll
        for (int d = 1; d < 32; d <<= 1) {
            int o = __shfl_down_sync(0xFFFFFFFFu, suf, d);
            if (tid + d < 32) suf += o;
        }
        int sufN = __shfl_down_sync(0xFFFFFFFFu, suf, 1);
        if (tid == 31) sufN = 0;
        if (tid == 0) { sh[0] = -1; sh[6] = 0; }
        __syncwarp();
        if (suf >= TOPK && sufN < TOPK) { sh[0] = tid; sh[1] = sufN; }
        __syncwarp();
        if (tid == 0 && sh[0] >= 0) {
            int cum = sh[1];
            int d = sh[0] * 32 + 31;
            for (;; d--) { cum += hist[d]; if (cum >= TOPK) break; }
            sh[3] = d;                // digit of 200th value
            sh[4] = cum - hist[d];    // count with digit > d
            sh[5] = hist[d];
        }
    }
    __syncthreads();

    int ncand;
    bool rare = (sh[0] >= 0) && (sh[4] + sh[5] > CAP);
    if (!rare) {
        // ---- P2 common: collect keys >= digit floor (<= 256 of them) ----
        uint32_t thrK = (sh[0] < 0) ? (BASE16 << 16)
                                    : ((uint32_t)(BASE16 + (uint32_t)sh[3]) << 16);
        for (int i = tid; i < TOPK; i += NTB) ssc[i] = -1.0f;
        for (int i = tid; i < NPRI4; i += NTB) {
            uint4 v = gk4[i];
            int base = i * 4;
            if (v.x >= thrK) { int p = atomicAdd(&sh[6], 1); spk[p] = ((unsigned long long)v.x << 32) | (uint32_t)~(uint32_t)(base + 0); }
            if (v.y >= thrK) { int p = atomicAdd(&sh[6], 1); spk[p] = ((unsigned long long)v.y << 32) | (uint32_t)~(uint32_t)(base + 1); }
            if (v.z >= thrK) { int p = atomicAdd(&sh[6], 1); spk[p] = ((unsigned long long)v.z << 32) | (uint32_t)~(uint32_t)(base + 2); }
            if (v.w >= thrK) { int p = atomicAdd(&sh[6], 1); spk[p] = ((unsigned long long)v.w << 32) | (uint32_t)~(uint32_t)(base + 3); }
        }
        __syncthreads();
        ncand = sh[6];
    } else {
        // ---- P2 rare (massive ties at the cut digit): exact 32-bit refine ----
        for (int i = tid; i < TOPK; i += NTB) ssc[i] = -1.0f;
        uint32_t top16 = BASE16 + (uint32_t)sh[3];
        int cnt_gt = sh[4];
        if (tid < 256) hist[tid] = 0;
        __syncthreads();
        for (int i = tid; i < NPRI; i += NTB) {
            uint32_t k = gk[i];
            if ((k >> 16) == top16) atomicAdd(&hist[(k >> 8) & 0xFF], 1);
        }
        __syncthreads();
        if (tid == 0) {
            int cum = cnt_gt; int d = 255;
            for (;; d--) { cum += hist[d]; if (cum >= TOPK) break; }
            sh[3] = d; sh[4] = cum - hist[d];
        }
        __syncthreads();
        uint32_t pre24 = (top16 << 8) | (uint32_t)sh[3];
        cnt_gt = sh[4];
        if (tid < 256) hist[tid] = 0;
        __syncthreads();
        for (int i = tid; i < NPRI; i += NTB) {
            uint32_t k = gk[i];
            if ((k >> 8) == pre24) atomicAdd(&hist[k & 0xFF], 1);
        }
        __syncthreads();
        if (tid == 0) {
            int cum = cnt_gt; int d = 255;
            for (;; d--) { cum += hist[d]; if (cum >= TOPK) break; }
            sh[3] = d;
        }
        __syncthreads();
        uint32_t thr = (pre24 << 8) | (uint32_t)sh[3];
        for (int i = tid; i < NPRI; i += NTB) {
            uint32_t k = gk[i];
            if (k > thr) { int p = atomicAdd(&sh[6], 1); spk[p] = ((unsigned long long)k << 32) | (uint32_t)~(uint32_t)i; }
        }
        __syncthreads();
        if (tid == 0) {   // append ties in ascending index order
            int p = sh[6];
            for (int i = 0; i < NPRI && p < TOPK; i++)
                if (gk[i] == thr) { spk[p++] = ((unsigned long long)thr << 32) | (uint32_t)~(uint32_t)i; }
            sh[6] = p;
        }
        __syncthreads();
        ncand = sh[6];
    }

    // ---- P3: exact rank (key desc, index asc) + gather; idle threads zero out ----
    if (tid < ncand) {
        unsigned long long mypk = spk[tid];
        int rank = 0;
#pragma unroll 4
        for (int j = 0; j < ncand; j++) rank += (spk[j] > mypk) ? 1 : 0;
        if (rank < TOPK) {
            uint32_t kk = (uint32_t)(mypk >> 32);
            uint32_t idx = ~(uint32_t)mypk;
            float4 bx = g_boxes[b][idx];
            ssc[rank] = __uint_as_float(kk);
            sbx[rank] = bx;
            sar[rank] = (bx.z - bx.x) * (bx.w - bx.y);
        }
    } else if (tid >= 256) {
        for (int i = tid - 256; i < TOPK * 5; i += NTB - 256) orow[i] = 0.0f;
    }
    __syncthreads();
    int nval = ncand < TOPK ? ncand : TOPK;

    // ---- P4: IoU suppression masks. Row i split: main thread (tid=i) does the
    //      low half of its words, helper (tid=200+i, i<184) does the high half.
    {
        int i = -1, w0 = 0, w1 = 0;
        if (tid < TOPK) {
            i = tid;
            int wl = i >> 5, span = NW - wl;
            int mine = (i < 184) ? ((span + 1) >> 1) : span;
            w0 = wl; w1 = wl + mine;
        } else if (tid - TOPK < 184) {
            i = tid - TOPK;
            int wl = i >> 5, span = NW - wl;
            w0 = wl + ((span + 1) >> 1); w1 = NW;
        }
        if (i >= 0 && i < nval) {
            if (tid < TOPK)
                for (int w = 0; w < (i >> 5); w++) sup[i * SUPW + w] = 0u;
            float4 A = sbx[i];
            float aa = sar[i];
            for (int w = w0; w < w1; w++) {
                int j0 = w * 32;
                uint32_t m = 0;
#pragma unroll
                for (int jj = 0; jj < 32; jj++) {
                    int j = j0 + jj;
                    float4 B = sbx[j];
                    float xx1 = fmaxf(A.x, B.x);
                    float yy1 = fmaxf(A.y, B.y);
                    float xx2 = fminf(A.z, B.z);
                    float yy2 = fminf(A.w, B.w);
                    float iw = fmaxf(xx2 - xx1, 0.0f);
                    float ih = fmaxf(yy2 - yy1, 0.0f);
                    float inter = iw * ih;
                    float uni = aa + sar[j] - inter;
                    uint32_t bit = 0;
                    if (inter > uni * NMS_HI) bit = 1u << jj;
                    else if (inter > uni * NMS_LO) {
                        // ambiguity band: exact reference formula
                        if (inter / fmaxf(uni, 1e-12f) > NMS_T) bit = 1u << jj;
                    }
                    m |= bit;
                }
                uint32_t um = (nval >= j0 + 32) ? 0xFFFFFFFFu
                             : ((nval > j0) ? ((1u << (nval - j0)) - 1u) : 0u);
                if (w == (i >> 5))
                    um = (i - j0 < 31) ? (um & (0xFFFFFFFFu << (i - j0 + 1))) : 0u;
                sup[i * SUPW + w] = m & um;
            }
        }
    }
    __syncthreads();

    // ---- P5: sequential NMS sweep + compaction positions (thread 0) ----
    if (tid == 0) {
        uint32_t alv[NW];
#pragma unroll
        for (int w = 0; w < NW; w++) alv[w] = 0xFFFFFFFFu;
#pragma unroll
        for (int g = 0; g < NW; g++) {
            for (int bit = 0; bit < 32; bit++) {
                int i = g * 32 + bit;
                if (i >= nval) break;
                if ((alv[g] >> bit) & 1u) {
#pragma unroll
                    for (int w = 0; w < NW; w++) alv[w] &= ~sup[i * SUPW + w];
                }
            }
        }
        int cnt = 0;
#pragma unroll
        for (int g = 0; g < NW; g++) {
            uint32_t aw = alv[g];
            for (int bit = 0; bit < 32; bit++) {
                int i = g * 32 + bit;
                if (i >= nval) break;
                spos[i] = ((aw >> bit) & 1u) ? cnt++ : -1;
            }
        }
    }
    __syncthreads();

    // ---- P6: write kept rows compacted to front ----
    for (int i = tid; i < nval; i += NTB) {
        int q = spos[i];
        if (q >= 0) {
            float* r = orow + q * 5;
            float4 bx = sbx[i];
            r[0] = ssc[i];
            r[1] = bx.x;
            r[2] = bx.y;
            r[3] = bx.z;
            r[4] = bx.w;
        }
    }
}

// ---------------------------------------------------------------------------
extern "C" void kernel_launch(void* const* d_in, const int* in_sizes, int n_in,
                              void* d_out, int out_size)
{
    const float* loc    = (const float*)d_in[0];
    const float* conf   = (const float*)d_in[1];
    const float* priors = (const float*)d_in[2];
    float* out = (float*)d_out;

    ssd_decode_softmax<<<(BATCH * NPRI + 255) / 256, 256>>>(loc, conf, priors);
    ssd_select_nms<<<BATCH * NCLS, NTB>>>(out);
}

// round 5
// speedup vs baseline: 3.6575x; 1.6366x over previous
#include <cuda_runtime.h>
#include <cstdint>

// ---------------------------------------------------------------------------
// SSD post-processing:
//   inputs:  loc [32,8732,4] f32, conf [32,8732,21] f32, priors [8732,4] f32
//   output:  [32,21,200,5] f32  rows = [score, x1, y1, x2, y2]
// ---------------------------------------------------------------------------

#define BATCH 32
#define NPRI  8732
#define NPRI4 2183          /* 8732 / 4 exactly */
#define NCLS  21
#define TOPK  200
#define CAP   256           /* candidate capacity (common path) */
#define NW    7             /* ceil(200/32) suppression words */
#define SUPW  8             /* padded row width */
#define NTB   384           /* threads per select block */
#define CITER 6             /* ceil(NPRI4 / NTB) */
#define CONF_T 0.01f
#define NMS_T  0.45f
#define NMS_HI 0.45000180f  /* 0.45*(1+4e-6) */
#define NMS_LO 0.44999820f  /* 0.45*(1-4e-6) */
#define BASE16 0x3C00u      /* top16 of float bits; all valid keys above this */

// scratch (module-load allocated, not runtime alloc)
__device__ __align__(16) uint32_t g_keys[BATCH][NCLS-1][NPRI];
__device__ float4 g_boxes[BATCH][NPRI];

// ---------------------------------------------------------------------------
// Kernel A: softmax + decode. One thread per (b, prior). HBM-roofline bound.
// ---------------------------------------------------------------------------
__global__ __launch_bounds__(256) void ssd_decode_softmax(
    const float* __restrict__ loc,
    const float* __restrict__ conf,
    const float* __restrict__ priors)
{
    int t = blockIdx.x * blockDim.x + threadIdx.x;
    if (t >= BATCH * NPRI) return;
    int b = t / NPRI;
    int p = t - b * NPRI;

    const float* cf = conf + (size_t)t * NCLS;
    float v[NCLS];
    float m = -1e30f;
#pragma unroll
    for (int c = 0; c < NCLS; c++) {
        float x = cf[c];
        x = fminf(fmaxf(x, -100.0f), 100.0f);
        v[c] = x;
        m = fmaxf(m, x);
    }
    float s = 0.0f;
#pragma unroll
    for (int c = 0; c < NCLS; c++) { v[c] = expf(v[c] - m); s += v[c]; }

    const float* lp = loc + (size_t)t * 4;
    const float* pr = priors + (size_t)p * 4;
    float p0 = fmaxf(pr[0], 1e-6f);
    float p1 = fmaxf(pr[1], 1e-6f);
    float p2 = fmaxf(pr[2], 1e-6f);
    float p3 = fmaxf(pr[3], 1e-6f);
    float cx = p0 + lp[0] * 0.1f * p2;
    float cy = p1 + lp[1] * 0.1f * p3;
    float lw = fminf(fmaxf(lp[2] * 0.2f, -4.0f), 4.0f);
    float lh = fminf(fmaxf(lp[3] * 0.2f, -4.0f), 4.0f);
    float w = p2 * expf(lw);
    float h = p3 * expf(lh);
    float x1 = fminf(fmaxf(cx - w / 2.0f, 0.0f), 1.0f);
    float y1 = fminf(fmaxf(cy - h / 2.0f, 0.0f), 1.0f);
    float x2 = fminf(fmaxf(cx + w / 2.0f, 0.0f), 1.0f);
    float y2 = fminf(fmaxf(cy + h / 2.0f, 0.0f), 1.0f);
    g_boxes[b][p] = make_float4(x1, y1, x2, y2);

    bool bvalid = (x2 > x1 + 1e-6f) && (y2 > y1 + 1e-6f);
#pragma unroll
    for (int c = 1; c < NCLS; c++) {
        float sc = v[c] / s;
        uint32_t key = (bvalid && sc > CONF_T) ? __float_as_uint(sc) : 0u;
        g_keys[b][c - 1][p] = key;
    }
}

// ---------------------------------------------------------------------------
// Kernel B: per (image,class): smem histogram select, warp-aggregated collect,
// O(n^2) exact rank, split-row IoU mask, warp-parallel sweep + compaction.
// 384 threads, 5 blocks/SM -> single wave for 672 blocks.
// ---------------------------------------------------------------------------
__global__ __launch_bounds__(NTB, 5) void ssd_select_nms(float* __restrict__ out)
{
    __shared__ int hist[1024];
    __shared__ int part[256];
    __shared__ unsigned long long spk[CAP];
    __shared__ uint32_t sup[TOPK * SUPW];
    __shared__ float4 sbx[224];          /* padded: IoU reads j up to 223 (masked) */
    __shared__ float sar[224], ssc[TOPK];
    __shared__ uint32_t salive[8];
    __shared__ int sbase[8];
    __shared__ int sh[8];

    int bc = blockIdx.x;
    int b = bc / NCLS;
    int c = bc - b * NCLS;
    int tid = threadIdx.x;
    int lane = tid & 31;
    float* orow = out + (size_t)bc * (TOPK * 5);

    if (c == 0) {
        for (int i = tid; i < TOPK * 5; i += NTB) orow[i] = 0.0f;
        return;
    }

    const uint32_t* gk = &g_keys[b][c - 1][0];
    const uint4* gk4 = (const uint4*)gk;

    // ---- P0: 16-bit digit histogram in smem (skip zero keys) ----
    for (int i = tid; i < 1024; i += NTB) hist[i] = 0;
    __syncthreads();
    for (int i = tid; i < NPRI4; i += NTB) {
        uint4 v = gk4[i];
        if (v.x) atomicAdd(&hist[(v.x >> 16) - BASE16], 1);
        if (v.y) atomicAdd(&hist[(v.y >> 16) - BASE16], 1);
        if (v.z) atomicAdd(&hist[(v.z >> 16) - BASE16], 1);
        if (v.w) atomicAdd(&hist[(v.w >> 16) - BASE16], 1);
    }
    __syncthreads();
    if (tid < 256) {
        int4 h4 = ((const int4*)hist)[tid];
        part[tid] = h4.x + h4.y + h4.z + h4.w;
    }
    __syncthreads();

    // ---- P1: warp 0 locates the 200th-largest digit via suffix scan ----
    if (tid < 32) {
        int s = 0;
#pragma unroll
        for (int q = 0; q < 8; q++) s += part[tid * 8 + q];
        int suf = s;
#pragma unroll
        for (int d = 1; d < 32; d <<= 1) {
            int o = __shfl_down_sync(0xFFFFFFFFu, suf, d);
            if (tid + d < 32) suf += o;
        }
        int sufN = __shfl_down_sync(0xFFFFFFFFu, suf, 1);
        if (tid == 31) sufN = 0;
        if (tid == 0) { sh[0] = -1; sh[6] = 0; }
        __syncwarp();
        if (suf >= TOPK && sufN < TOPK) { sh[0] = tid; sh[1] = sufN; }
        __syncwarp();
        if (tid == 0 && sh[0] >= 0) {
            int cum = sh[1];
            int d = sh[0] * 32 + 31;
            for (;; d--) { cum += hist[d]; if (cum >= TOPK) break; }
            sh[3] = d;                // digit of 200th value
            sh[4] = cum - hist[d];    // count with digit > d
            sh[5] = hist[d];
        }
    }
    __syncthreads();

    int ncand;
    bool rare = (sh[0] >= 0) && (sh[4] + sh[5] > CAP);
    if (!rare) {
        // ---- P2 common: collect keys >= digit floor, warp-aggregated push ----
        uint32_t thrK = (sh[0] < 0) ? (BASE16 << 16)
                                    : ((uint32_t)(BASE16 + (uint32_t)sh[3]) << 16);
        for (int i = tid; i < TOPK; i += NTB) ssc[i] = -1.0f;
#pragma unroll
        for (int it = 0; it < CITER; it++) {
            int i = tid + it * NTB;
            uint4 v = (i < NPRI4) ? gk4[i] : make_uint4(0u, 0u, 0u, 0u);
            int base4 = i * 4;
#pragma unroll
            for (int comp = 0; comp < 4; comp++) {
                uint32_t k = (comp == 0) ? v.x : (comp == 1) ? v.y : (comp == 2) ? v.z : v.w;
                int take = (k >= thrK);
                uint32_t bm = __ballot_sync(0xFFFFFFFFu, take);
                if (bm) {
                    int ldr = __ffs(bm) - 1;
                    int pos = 0;
                    if (lane == ldr) pos = atomicAdd(&sh[6], __popc(bm));
                    pos = __shfl_sync(0xFFFFFFFFu, pos, ldr);
                    if (take) {
                        int off = __popc(bm & ((1u << lane) - 1u));
                        spk[pos + off] = ((unsigned long long)k << 32)
                                       | (uint32_t)~(uint32_t)(base4 + comp);
                    }
                }
            }
        }
        __syncthreads();
        ncand = sh[6];
    } else {
        // ---- P2 rare (massive ties at cut digit): exact 32-bit refine ----
        for (int i = tid; i < TOPK; i += NTB) ssc[i] = -1.0f;
        uint32_t top16 = BASE16 + (uint32_t)sh[3];
        int cnt_gt = sh[4];
        if (tid < 256) hist[tid] = 0;
        __syncthreads();
        for (int i = tid; i < NPRI; i += NTB) {
            uint32_t k = gk[i];
            if ((k >> 16) == top16) atomicAdd(&hist[(k >> 8) & 0xFF], 1);
        }
        __syncthreads();
        if (tid == 0) {
            int cum = cnt_gt; int d = 255;
            for (;; d--) { cum += hist[d]; if (cum >= TOPK) break; }
            sh[3] = d; sh[4] = cum - hist[d];
        }
        __syncthreads();
        uint32_t pre24 = (top16 << 8) | (uint32_t)sh[3];
        cnt_gt = sh[4];
        if (tid < 256) hist[tid] = 0;
        __syncthreads();
        for (int i = tid; i < NPRI; i += NTB) {
            uint32_t k = gk[i];
            if ((k >> 8) == pre24) atomicAdd(&hist[k & 0xFF], 1);
        }
        __syncthreads();
        if (tid == 0) {
            int cum = cnt_gt; int d = 255;
            for (;; d--) { cum += hist[d]; if (cum >= TOPK) break; }
            sh[3] = d;
        }
        __syncthreads();
        uint32_t thr = (pre24 << 8) | (uint32_t)sh[3];
        for (int i = tid; i < NPRI; i += NTB) {
            uint32_t k = gk[i];
            if (k > thr) { int p = atomicAdd(&sh[6], 1); spk[p] = ((unsigned long long)k << 32) | (uint32_t)~(uint32_t)i; }
        }
        __syncthreads();
        if (tid == 0) {   // append ties in ascending index order
            int p = sh[6];
            for (int i = 0; i < NPRI && p < TOPK; i++)
                if (gk[i] == thr) { spk[p++] = ((unsigned long long)thr << 32) | (uint32_t)~(uint32_t)i; }
            sh[6] = p;
        }
        __syncthreads();
        ncand = sh[6];
    }

    // ---- P3: exact rank (key desc, index asc) + gather; idle threads zero out ----
    if (tid < ncand) {
        unsigned long long mypk = spk[tid];
        int rank = 0;
#pragma unroll 4
        for (int j = 0; j < ncand; j++) rank += (spk[j] > mypk) ? 1 : 0;
        if (rank < TOPK) {
            uint32_t kk = (uint32_t)(mypk >> 32);
            uint32_t idx = ~(uint32_t)mypk;
            float4 bx = g_boxes[b][idx];
            ssc[rank] = __uint_as_float(kk);
            sbx[rank] = bx;
            sar[rank] = (bx.z - bx.x) * (bx.w - bx.y);
        }
    } else if (tid >= 256) {
        for (int i = tid - 256; i < TOPK * 5; i += NTB - 256) orow[i] = 0.0f;
    }
    __syncthreads();
    int nval = ncand < TOPK ? ncand : TOPK;

    // ---- P4: IoU suppression masks. Row i split: main thread (tid=i) does the
    //      low half of its word span, helper (tid=200+i, i<184) the high half.
    {
        int i = -1, w0 = 0, w1 = 0;
        if (tid < TOPK) {
            i = tid;
            int wl = i >> 5, span = NW - wl;
            int mine = (i < 184) ? ((span + 1) >> 1) : span;
            w0 = wl; w1 = wl + mine;
        } else if (tid - TOPK < 184) {
            i = tid - TOPK;
            int wl = i >> 5, span = NW - wl;
            w0 = wl + ((span + 1) >> 1); w1 = NW;
        }
        if (i >= 0 && i < nval) {
            if (tid < TOPK)
                for (int w = 0; w < (i >> 5); w++) sup[i * SUPW + w] = 0u;
            float4 A = sbx[i];
            float aa = sar[i];
            for (int w = w0; w < w1; w++) {
                int j0 = w * 32;
                uint32_t m = 0;
#pragma unroll
                for (int jj = 0; jj < 32; jj++) {
                    int j = j0 + jj;
                    float4 B = sbx[j];
                    float xx1 = fmaxf(A.x, B.x);
                    float yy1 = fmaxf(A.y, B.y);
                    float xx2 = fminf(A.z, B.z);
                    float yy2 = fminf(A.w, B.w);
                    float iw = fmaxf(xx2 - xx1, 0.0f);
                    float ih = fmaxf(yy2 - yy1, 0.0f);
                    float inter = iw * ih;
                    float uni = aa + sar[j] - inter;
                    uint32_t bit = 0;
                    if (inter > uni * NMS_HI) bit = 1u << jj;
                    else if (inter > uni * NMS_LO) {
                        if (inter / fmaxf(uni, 1e-12f) > NMS_T) bit = 1u << jj;  // exact ref
                    }
                    m |= bit;
                }
                uint32_t um = (nval >= j0 + 32) ? 0xFFFFFFFFu
                             : ((nval > j0) ? ((1u << (nval - j0)) - 1u) : 0u);
                if (w == (i >> 5))
                    um = (i - j0 < 31) ? (um & (0xFFFFFFFFu << (i - j0 + 1))) : 0u;
                sup[i * SUPW + w] = m & um;
            }
        }
    }
    __syncthreads();

    // ---- P5: warp-parallel NMS sweep (warp 0) + popc compaction bases ----
    if (tid < 32) {
        uint32_t alive_w = 0xFFFFFFFFu;
        int nchunks = (nval + 31) >> 5;
        for (int g = 0; g < nchunks; g++) {
            int rem = nval - g * 32;
            uint32_t vm = (rem >= 32) ? 0xFFFFFFFFu : ((1u << rem) - 1u);
            uint32_t ag = __shfl_sync(0xFFFFFFFFu, alive_w, g) & vm;
            // intra-chunk serial resolve via shuffles (register chain, no LDS)
            uint32_t selfm = (lane < rem) ? sup[(g * 32 + lane) * SUPW + g] : 0u;
#pragma unroll
            for (int bit = 0; bit < 32; bit++) {
                uint32_t sm = __shfl_sync(0xFFFFFFFFu, selfm, bit);
                if ((ag >> bit) & 1u) ag &= ~sm;
            }
            if (lane == g) alive_w = ag;
            // apply chunk g's alive rows to later words (independent LDS, pipelined)
            uint32_t acc = 0;
            int waddr = (lane < NW) ? lane : NW - 1;
#pragma unroll
            for (int bit = 0; bit < 32; bit++) {
                uint32_t s = (bit < rem) ? sup[(g * 32 + bit) * SUPW + waddr] : 0u;
                if ((ag >> bit) & 1u) acc |= s;
            }
            if (lane > g && lane < NW) alive_w &= ~acc;
        }
        uint32_t aw = (lane < NW && lane < nchunks) ? alive_w : 0u;
        // mask final chunk's invalid tail
        if (lane == nchunks - 1) {
            int rem = nval - lane * 32;
            if (rem < 32) aw &= ((1u << (rem > 0 ? rem : 0)) - 1u);
        }
        int pc = __popc(aw);
        int pre = pc;
#pragma unroll
        for (int d = 1; d < 32; d <<= 1) {
            int o = __shfl_up_sync(0xFFFFFFFFu, pre, d);
            if (lane >= d) pre += o;
        }
        if (lane < NW) { salive[lane] = aw; sbase[lane] = pre - pc; }
    }
    __syncthreads();

    // ---- P6: write kept rows compacted to front ----
    for (int i = tid; i < nval; i += NTB) {
        int w = i >> 5, bit = i & 31;
        uint32_t aw = salive[w];
        if ((aw >> bit) & 1u) {
            int q = sbase[w] + __popc(aw & ((1u << bit) - 1u));
            float* r = orow + q * 5;
            float4 bx = sbx[i];
            r[0] = ssc[i];
            r[1] = bx.x;
            r[2] = bx.y;
            r[3] = bx.z;
            r[4] = bx.w;
        }
    }
}

// ---------------------------------------------------------------------------
extern "C" void kernel_launch(void* const* d_in, const int* in_sizes, int n_in,
                              void* d_out, int out_size)
{
    const float* loc    = (const float*)d_in[0];
    const float* conf   = (const float*)d_in[1];
    const float* priors = (const float*)d_in[2];
    float* out = (float*)d_out;

    ssd_decode_softmax<<<(BATCH * NPRI + 255) / 256, 256>>>(loc, conf, priors);
    ssd_select_nms<<<BATCH * NCLS, NTB>>>(out);
}